// round 6
// baseline (speedup 1.0000x reference)
#include <cuda_runtime.h>
#include <math.h>

#define NU 100000
#define NI 50000
#define DD 128
#define CC 5
#define EE 200000
#define LL 10
#define TB 32           // edges (rows) per block
#define PITCH 132       // smem row pitch (floats): 132*4B, 8-lane phases conflict-free

// ---------------- scratch (static device memory; no allocation at runtime) ----
__device__ float g_ur1[(size_t)NU * DD];
__device__ float g_ir1[(size_t)NI * DD];
__device__ float g_ut1[(size_t)NU * DD];
__device__ float g_it1[(size_t)NI * DD];
__device__ float g_partial[EE / TB];

// ---------------- register-tiled 32xK(=128)x128 GEMM on a smem tile -----------
// Thread map: 128 threads. jx = tid>>2 (column group, cols jx*4..jx*4+3),
// ex = tid&3 (edge group, rows ex, ex+4, ..., ex+28).
// Per 4-k chunk: 4 coalesced LDG.128 of W rows + 8 broadcast LDS.128 of X rows
// + 128 FFMA -> ~91% FFMA issue density.
__device__ __forceinline__ void gemm_tile(const float Xs[TB][PITCH],
                                          const float* __restrict__ W,
                                          int jx, int ex, float acc[8][4]) {
#pragma unroll 2
    for (int k = 0; k < 128; k += 4) {
        const float* wb = W + k * 128 + (jx << 2);
        const float4 w0 = *(const float4*)(wb);
        const float4 w1 = *(const float4*)(wb + 128);
        const float4 w2 = *(const float4*)(wb + 256);
        const float4 w3 = *(const float4*)(wb + 384);
#pragma unroll
        for (int i = 0; i < 8; i++) {
            const float4 x = *(const float4*)&Xs[ex + (i << 2)][k];
            acc[i][0] = fmaf(x.x, w0.x, acc[i][0]);
            acc[i][1] = fmaf(x.x, w0.y, acc[i][1]);
            acc[i][2] = fmaf(x.x, w0.z, acc[i][2]);
            acc[i][3] = fmaf(x.x, w0.w, acc[i][3]);
            acc[i][0] = fmaf(x.y, w1.x, acc[i][0]);
            acc[i][1] = fmaf(x.y, w1.y, acc[i][1]);
            acc[i][2] = fmaf(x.y, w1.z, acc[i][2]);
            acc[i][3] = fmaf(x.y, w1.w, acc[i][3]);
            acc[i][0] = fmaf(x.z, w2.x, acc[i][0]);
            acc[i][1] = fmaf(x.z, w2.y, acc[i][1]);
            acc[i][2] = fmaf(x.z, w2.z, acc[i][2]);
            acc[i][3] = fmaf(x.z, w2.w, acc[i][3]);
            acc[i][0] = fmaf(x.w, w3.x, acc[i][0]);
            acc[i][1] = fmaf(x.w, w3.y, acc[i][1]);
            acc[i][2] = fmaf(x.w, w3.z, acc[i][2]);
            acc[i][3] = fmaf(x.w, w3.w, acc[i][3]);
        }
    }
}

// ---------------- K1: precompute per-node transforms Y = X @ W (K=128) -------
// which: 0->g_ur1, 1->g_ir1, 2->g_ut1, 3->g_it1
__global__ __launch_bounds__(128) void k_pre(const float* __restrict__ X,
                                             const float* __restrict__ W,
                                             int N, int which) {
    __shared__ float Xs[TB][PITCH];
    float* Y = (which == 0) ? g_ur1 : (which == 1) ? g_ir1 : (which == 2) ? g_ut1 : g_it1;
    const int tid = threadIdx.x;
    const int row0 = blockIdx.x << 5;

#pragma unroll
    for (int rep = 0; rep < 8; rep++) {
        int idx = (rep << 7) + tid;          // 0..1023 float4 slots
        int r = idx >> 5, c4 = idx & 31;
        float4 v = make_float4(0.f, 0.f, 0.f, 0.f);
        int row = row0 + r;
        if (row < N) v = *(const float4*)(X + (size_t)row * DD + (c4 << 2));
        *(float4*)&Xs[r][c4 << 2] = v;
    }
    __syncthreads();

    const int jx = tid >> 2, ex = tid & 3;
    float acc[8][4];
#pragma unroll
    for (int i = 0; i < 8; i++)
#pragma unroll
        for (int c = 0; c < 4; c++) acc[i][c] = 0.f;

    gemm_tile(Xs, W, jx, ex, acc);

#pragma unroll
    for (int i = 0; i < 8; i++) {
        int row = row0 + ex + (i << 2);
        if (row < N)
            *(float4*)(Y + (size_t)row * DD + (jx << 2)) =
                make_float4(acc[i][0], acc[i][1], acc[i][2], acc[i][3]);
    }
}

// gather 32 rows: A[r][:] = relu(U[src[r]][:] + I[dst[r]][:])
__device__ __forceinline__ void gather_relu(float A[TB][PITCH],
                                            const float* __restrict__ U,
                                            const float* __restrict__ I,
                                            const int* s_src, const int* s_dst,
                                            int tid) {
#pragma unroll
    for (int rep = 0; rep < 8; rep++) {
        int idx = (rep << 7) + tid;
        int r = idx >> 5, c4 = idx & 31;
        const float4 u = *(const float4*)(U + (size_t)s_src[r] * DD + (c4 << 2));
        const float4 v = *(const float4*)(I + (size_t)s_dst[r] * DD + (c4 << 2));
        float4 h;
        h.x = fmaxf(u.x + v.x, 0.f);
        h.y = fmaxf(u.y + v.y, 0.f);
        h.z = fmaxf(u.z + v.z, 0.f);
        h.w = fmaxf(u.w + v.w, 0.f);
        *(float4*)&A[r][c4 << 2] = h;
    }
}

// ---------------- K2: per-edge fused kernel ----------------------------------
__global__ __launch_bounds__(128) void k_edge(const float* __restrict__ w2r,
                                              const float* __restrict__ w2t,
                                              const float* __restrict__ wp,
                                              const float* __restrict__ emb,
                                              const int* __restrict__ src,
                                              const int* __restrict__ dst,
                                              const int* __restrict__ sid,
                                              const int* __restrict__ nsid,
                                              float* __restrict__ out_pr) {
    __shared__ float A[TB][PITCH];   // h1 (rating), then h1 (topic), then th
    __shared__ float B[TB][PITCH];   // rh
    __shared__ int s_src[TB], s_dst[TB];
    __shared__ float s_wloss[4];

    const int tid = threadIdx.x;
    const int e0 = blockIdx.x * TB;

    if (tid < TB) {
        s_src[tid] = src[e0 + tid];
        s_dst[tid] = dst[e0 + tid];
    }
    __syncthreads();

    const int jx = tid >> 2, ex = tid & 3;
    const int wid = tid >> 5, lane = tid & 31;

    // ---- rating: h1 = relu(ur1[src]+ir1[dst]); rh = h1 @ w2r ----
    gather_relu(A, g_ur1, g_ir1, s_src, s_dst, tid);
    __syncthreads();

    float acc[8][4];
#pragma unroll
    for (int i = 0; i < 8; i++)
#pragma unroll
        for (int c = 0; c < 4; c++) acc[i][c] = 0.f;
    gemm_tile(A, w2r, jx, ex, acc);

#pragma unroll
    for (int i = 0; i < 8; i++)
        *(float4*)&B[ex + (i << 2)][jx << 2] =
            make_float4(acc[i][0], acc[i][1], acc[i][2], acc[i][3]);
    __syncthreads();   // B ready; all A reads done

    // ---- pr = rh @ wp : each warp covers edges wid, wid+4, ... ----
    for (int e = wid; e < TB; e += 4) {
        float p0 = 0.f, p1 = 0.f, p2 = 0.f, p3 = 0.f, p4 = 0.f;
#pragma unroll
        for (int q = 0; q < 4; q++) {
            int k = lane + (q << 5);
            float h = B[e][k];
            const float* wrow = wp + k * CC;
            p0 = fmaf(h, wrow[0], p0);
            p1 = fmaf(h, wrow[1], p1);
            p2 = fmaf(h, wrow[2], p2);
            p3 = fmaf(h, wrow[3], p3);
            p4 = fmaf(h, wrow[4], p4);
        }
#pragma unroll
        for (int off = 16; off; off >>= 1) {
            p0 += __shfl_down_sync(0xffffffffu, p0, off);
            p1 += __shfl_down_sync(0xffffffffu, p1, off);
            p2 += __shfl_down_sync(0xffffffffu, p2, off);
            p3 += __shfl_down_sync(0xffffffffu, p3, off);
            p4 += __shfl_down_sync(0xffffffffu, p4, off);
        }
        if (lane == 0) {
            float* o = out_pr + (size_t)(e0 + e) * CC;
            o[0] = p0; o[1] = p1; o[2] = p2; o[3] = p3; o[4] = p4;
        }
    }

    // ---- topic: h1t = relu(ut1[src]+it1[dst]); th = h1t @ w2t + rh ----
    gather_relu(A, g_ut1, g_it1, s_src, s_dst, tid);   // A free after last sync
    __syncthreads();

#pragma unroll
    for (int i = 0; i < 8; i++)
#pragma unroll
        for (int c = 0; c < 4; c++) acc[i][c] = 0.f;
    gemm_tile(A, w2t, jx, ex, acc);
    __syncthreads();   // all A reads done before overwrite with th

#pragma unroll
    for (int i = 0; i < 8; i++) {
        const float4 rh = *(const float4*)&B[ex + (i << 2)][jx << 2];
        *(float4*)&A[ex + (i << 2)][jx << 2] =
            make_float4(acc[i][0] + rh.x, acc[i][1] + rh.y,
                        acc[i][2] + rh.z, acc[i][3] + rh.w);
    }
    __syncthreads();   // th ready in A

    // ---- reviews + BPR loss: each warp covers edges wid, wid+4, ... ----
    float wsum = 0.f;
    for (int e = wid; e < TB; e += 4) {
        const int eg = e0 + e;
        const float4 th4 = *(const float4*)&A[e][lane << 2];

        float4 ps = make_float4(0.f, 0.f, 0.f, 0.f);
        float pcnt = 0.f;
#pragma unroll
        for (int l = 0; l < LL; l++) {
            int s = __ldg(sid + (size_t)eg * LL + l);      // uniform across warp
            const float4 v = __ldg((const float4*)(emb + (size_t)s * DD) + lane);
            ps.x += v.x; ps.y += v.y; ps.z += v.z; ps.w += v.w;
            pcnt += (s > 0) ? 1.f : 0.f;
        }
        float4 ns = make_float4(0.f, 0.f, 0.f, 0.f);
        float ncnt = 0.f;
#pragma unroll
        for (int l = 0; l < LL; l++) {
            int s = __ldg(nsid + (size_t)eg * LL + l);
            const float4 v = __ldg((const float4*)(emb + (size_t)s * DD) + lane);
            ns.x += v.x; ns.y += v.y; ns.z += v.z; ns.w += v.w;
            ncnt += (s > 0) ? 1.f : 0.f;
        }

        float pd = th4.x * ps.x + th4.y * ps.y + th4.z * ps.z + th4.w * ps.w;
        float nd = th4.x * ns.x + th4.y * ns.y + th4.z * ns.z + th4.w * ns.w;
#pragma unroll
        for (int off = 16; off; off >>= 1) {
            pd += __shfl_down_sync(0xffffffffu, pd, off);
            nd += __shfl_down_sync(0xffffffffu, nd, off);
        }
        if (lane == 0) {
            float pos = pd / (pcnt + 1e-9f);
            float neg = nd / (ncnt + 1e-9f);
            float z = neg - pos;                 // loss = softplus(-(pos-neg))
            float loss = fmaxf(z, 0.f) + log1pf(expf(-fabsf(z)));
            wsum += loss;
        }
    }
    if (lane == 0) s_wloss[wid] = wsum;
    __syncthreads();
    if (tid == 0)
        g_partial[blockIdx.x] = s_wloss[0] + s_wloss[1] + s_wloss[2] + s_wloss[3];
}

// ---------------- K3: deterministic loss reduction ---------------------------
__global__ __launch_bounds__(256) void k_reduce(float* __restrict__ out, int out_size) {
    __shared__ float s[256];
    float v = 0.f;
    for (int i = threadIdx.x; i < EE / TB; i += 256) v += g_partial[i];
    s[threadIdx.x] = v;
    __syncthreads();
    for (int st = 128; st; st >>= 1) {
        if (threadIdx.x < st) s[threadIdx.x] += s[threadIdx.x + st];
        __syncthreads();
    }
    if (threadIdx.x == 0) {
        float mean = s[0] / (float)EE;
        for (int i = EE * CC; i < out_size; i++) out[i] = mean;
    }
}

// ---------------- launch -----------------------------------------------------
extern "C" void kernel_launch(void* const* d_in, const int* in_sizes, int n_in,
                              void* d_out, int out_size) {
    const float* urf = (const float*)d_in[0];
    const float* irf = (const float*)d_in[1];
    const float* utf = (const float*)d_in[2];
    const float* itf = (const float*)d_in[3];
    const float* w1r = (const float*)d_in[4];
    const float* w2r = (const float*)d_in[5];
    const float* w1t = (const float*)d_in[6];
    const float* w2t = (const float*)d_in[7];
    const float* wp  = (const float*)d_in[8];
    const float* emb = (const float*)d_in[9];
    const int* src  = (const int*)d_in[10];
    const int* dst  = (const int*)d_in[11];
    const int* sid  = (const int*)d_in[12];
    const int* nsid = (const int*)d_in[13];
    float* out = (float*)d_out;

    const int gu = (NU + TB - 1) / TB;
    const int gi = (NI + TB - 1) / TB;

    k_pre<<<gu, 128>>>(urf, w1r, NU, 0);                 // ur1 = urf @ w1r[:128]
    k_pre<<<gi, 128>>>(irf, w1r + 128 * 128, NI, 1);     // ir1 = irf @ w1r[128:]
    k_pre<<<gu, 128>>>(utf, w1t, NU, 2);                 // ut1 = utf @ w1t[:128]
    k_pre<<<gi, 128>>>(itf, w1t + 128 * 128, NI, 3);     // it1 = itf @ w1t[128:]

    k_edge<<<EE / TB, 128>>>(w2r, w2t, wp, emb, src, dst, sid, nsid, out);
    k_reduce<<<1, 256>>>(out, out_size);
}